// round 16
// baseline (speedup 1.0000x reference)
#include <cuda_runtime.h>
#include <cuda_bf16.h>
#include <cstdint>
#include <cstddef>

#define NU      100
#define TSTEPS  60
#define BTOT    8192
static const size_t OFFU  = 0;
static const size_t OFFT  = 3440640;
static const size_t OFFRS = 3932160;
static const size_t OFFL  = 4423680;
static const size_t OFFR  = 4431872;
static const size_t OFFZ  = 4440064;
static const size_t OFFYF = 4931584;

#define NSCALE 0.09486832980505138f

// GEMM per block per step: D[112,64] = A[112 x 112] * B[64 x 112]^T, bf16 3-split, fp32 acc.
// A rows 0-99 = Wrec, row 100 = w_out, rows 101-111 = 0. k-col 111 = b_rec. B col 111 = 1.
// 512 threads = 16 warps; warp = (mw, nw): mw = warp>>1 owns M rows 16mw..16mw+15 (mw<7),
// nw = warp&1 = trial-HALF h owns N cols 32h..32h+31. The two halves are fully
// independent per step (share only read-only A) and sync via named barriers 1+h.
#define PITCH 272
#define SA_H 0
#define SA_M 30464
#define SA_L 60928
#define SB_H 91392
#define SB_M 108800
#define SB_L 126208
#define S_NZ   143616   // 2 halves x 32 trials x 108 floats
#define S_STIM 171264
#define S_CAB  171520
#define SMEM_TOTAL 172032

__device__ __forceinline__ uint32_t smem_u32(const void* p){
    uint32_t a;
    asm("{ .reg .u64 t; cvta.to.shared.u64 t, %1; cvt.u32.u64 %0, t; }" : "=r"(a) : "l"(p));
    return a;
}
__device__ __forceinline__ void ldsm4(uint32_t addr, uint32_t &r0, uint32_t &r1, uint32_t &r2, uint32_t &r3){
    asm volatile("ldmatrix.sync.aligned.m8n8.x4.shared.b16 {%0,%1,%2,%3}, [%4];"
        : "=r"(r0), "=r"(r1), "=r"(r2), "=r"(r3) : "r"(addr));
}
__device__ __forceinline__ void hmma(float* c, uint32_t a0, uint32_t a1, uint32_t a2, uint32_t a3,
                                     uint32_t b0, uint32_t b1){
    asm volatile("mma.sync.aligned.m16n8k16.row.col.f32.bf16.bf16.f32 "
        "{%0,%1,%2,%3},{%4,%5,%6,%7},{%8,%9},{%0,%1,%2,%3};"
        : "+f"(c[0]), "+f"(c[1]), "+f"(c[2]), "+f"(c[3])
        : "r"(a0), "r"(a1), "r"(a2), "r"(a3), "r"(b0), "r"(b1));
}
__device__ __forceinline__ void split_store(char* bh, char* bm, char* bl, int off, float v){
    __nv_bfloat16 h = __float2bfloat16_rn(v);
    float r = v - __bfloat162float(h);
    __nv_bfloat16 m = __float2bfloat16_rn(r);
    r -= __bfloat162float(m);
    *(__nv_bfloat16*)(bh + off) = h;
    *(__nv_bfloat16*)(bm + off) = m;
    *(__nv_bfloat16*)(bl + off) = __float2bfloat16_rn(r);
}
#define HBAR() asm volatile("bar.sync %0, %1;" :: "r"(1 + hh), "r"(256) : "memory")

__global__ __launch_bounds__(512)
void rnn_hmma_kernel(
    const float* __restrict__ y0,      const float* __restrict__ noise,
    const int*   __restrict__ stimI,   const int*   __restrict__ rewI,
    const int*   __restrict__ instrI,
    const float* __restrict__ WinRaw,  const float* __restrict__ Wrec,
    const float* __restrict__ brec,    const float* __restrict__ wout,
    const float* __restrict__ bout,
    float* __restrict__ out)
{
    extern __shared__ char smc[];
    const uint32_t smb = smem_u32(smc);
    float*  smNz   = reinterpret_cast<float*>(smc + S_NZ);
    int*    smStim = reinterpret_cast<int*>(smc + S_STIM);
    float2* smCab  = reinterpret_cast<float2*>(smc + S_CAB);

    const int tid  = threadIdx.x;
    const int lane = tid & 31;
    const int warp = tid >> 5;
    const int bb   = blockIdx.x * 64;

    // ---- zero A/B split buffers ----
    for (int i = tid; i < S_NZ/16; i += 512)
        reinterpret_cast<uint4*>(smc)[i] = make_uint4(0,0,0,0);
    __syncthreads();

    // ---- fill A splits ----
    for (int idx = tid; idx < NU*NU; idx += 512) {
        int m = idx / NU, k = idx - m*NU;
        split_store(smc+SA_H, smc+SA_M, smc+SA_L, m*PITCH + 2*k, Wrec[idx]);
    }
    for (int k = tid; k < NU; k += 512)
        split_store(smc+SA_H, smc+SA_M, smc+SA_L, 100*PITCH + 2*k, wout[k]);
    for (int m = tid; m < NU; m += 512)
        split_store(smc+SA_H, smc+SA_M, smc+SA_L, m*PITCH + 2*111, brec[m]);
    for (int n = tid; n < 64; n += 512)
        *(__nv_bfloat16*)(smc + SB_H + n*PITCH + 2*111) = __float2bfloat16_rn(1.0f);
    for (int idx = tid; idx < 64*NU; idx += 512) {
        int n = idx / NU, k = idx - n*NU;
        split_store(smc+SB_H, smc+SB_M, smc+SB_L, n*PITCH + 2*k, y0[(size_t)(bb + n)*NU + k]);
    }
    if (tid < 64) smStim[tid] = stimI[bb + tid];

    const float b0 = bout[0];

    // ---- per-thread MMA geometry ----
    const int g = lane >> 2, q = lane & 3;
    const int mw = warp >> 1, hh = warp & 1;
    const int m0 = 16*mw, n0 = 32*hh;
    const int u0 = m0 + g, u1 = u0 + 8;
    const bool act = (mw < 7);
    const bool v0 = act && (u0 < NU);
    const bool v1 = act && (u1 < NU);
    const int hid = mw*32 + lane;              // 0..255 within half
    const bool isSM = (mw == 6) && (g == 4);   // state-machine threads (hold logit row)

    float4 wiA = make_float4(0,0,0,0), wiB = make_float4(0,0,0,0);
    float w4A=0,w5A=0,w6A=0,w4B=0,w5B=0,w6B=0;
    if (v0) {
        wiA = make_float4(fabsf(WinRaw[u0*7+0]), fabsf(WinRaw[u0*7+1]),
                          fabsf(WinRaw[u0*7+2]), fabsf(WinRaw[u0*7+3]));
        w4A = fabsf(WinRaw[u0*7+4]); w5A = fabsf(WinRaw[u0*7+5]); w6A = fabsf(WinRaw[u0*7+6]);
    }
    if (v1) {
        wiB = make_float4(fabsf(WinRaw[u1*7+0]), fabsf(WinRaw[u1*7+1]),
                          fabsf(WinRaw[u1*7+2]), fabsf(WinRaw[u1*7+3]));
        w4B = fabsf(WinRaw[u1*7+4]); w5B = fabsf(WinRaw[u1*7+5]); w6B = fabsf(WinRaw[u1*7+6]);
    }

    // ---- state-machine registers (only meaningful in isSM threads) ----
    // trial s (0..7) -> col = n0 + 8*(s>>1) + 2*q + (s&1); logit = c[s>>1][s&1]
    unsigned licM = 0, insFM = 0, iAM = 0, isRewM8 = 0, insBM8 = 0;
    int lickT8[8];
    #pragma unroll
    for (int s = 0; s < 8; s++) lickT8[s] = TSTEPS + 1;
    if (isSM) {
        #pragma unroll
        for (int s = 0; s < 8; s++) {
            int col = n0 + 8*(s>>1) + 2*q + (s&1);
            int b = bb + col;
            if (stimI[b] == rewI[b]) isRewM8 |= 1u << s;
            if (instrI[b] > 0)       insBM8 |= 1u << s;
        }
    }

    // y state: 2 units x 8 cols; col(nt,e) = n0 + 8*nt + 2*q + e, nt<4
    float yA[8], yB[8];
    #pragma unroll
    for (int nt = 0; nt < 4; nt++) {
        int col = n0 + 8*nt + 2*q;
        yA[2*nt]   = v0 ? y0[(size_t)(bb+col  )*NU + u0] : 0.0f;
        yA[2*nt+1] = v0 ? y0[(size_t)(bb+col+1)*NU + u0] : 0.0f;
        yB[2*nt]   = v1 ? y0[(size_t)(bb+col  )*NU + u1] : 0.0f;
        yB[2*nt+1] = v1 ? y0[(size_t)(bb+col+1)*NU + u1] : 0.0f;
    }

    // ldmatrix per-lane address components
    const uint32_t rbA = (uint32_t)(((lane & 7) + ((lane >> 3) & 1)*8)*PITCH + ((lane >> 4) & 1)*16);
    const uint32_t rbB = (uint32_t)(((lane & 7) + ((lane >> 4) & 1)*8)*PITCH + ((lane >> 3) & 1)*16);
    const uint32_t aBase = smb + SA_H + (uint32_t)m0*PITCH + rbA;
    const uint32_t bBase = smb + SB_H + (uint32_t)n0*PITCH + rbB;

    float* nzH = smNz + hh*3456;   // this half's noise buffer (32 trials x 108)

    __syncthreads();

    // ==================== time loop (61 rounds; halves sync independently) ====================
    for (int t = 0; t <= TSTEPS; t++) {
        const bool last = (t == TSTEPS);

        // ---- stage this half's noise (regs now, smem after MMA) ----
        float4 stg[4];
        if (!last) {
            #pragma unroll
            for (int i = 0; i < 4; i++) {
                int idx = hid + 256*i;
                if (idx < 800) {
                    int trl = idx / 25, qq = idx - 25*trl;
                    stg[i] = *reinterpret_cast<const float4*>(
                        noise + (size_t)(bb + n0 + trl)*(TSTEPS*NU) + (size_t)t*NU + 4*qq);
                }
            }
        }

        // ---- MMA: 6 split-passes, k-grouped; 16x32 D tile per warp ----
        float c[4][4];
        #pragma unroll
        for (int nt = 0; nt < 4; nt++) { c[nt][0]=0.f; c[nt][1]=0.f; c[nt][2]=0.f; c[nt][3]=0.f; }
        if (act) {
            #pragma unroll
            for (int ks = 0; ks < 7; ks++) {
                uint32_t aH0,aH1,aH2,aH3, aM0,aM1,aM2,aM3, aL0,aL1,aL2,aL3;
                uint32_t aAddr = aBase + 32*ks;
                ldsm4(aAddr,                 aH0,aH1,aH2,aH3);
                ldsm4(aAddr + (SA_M - SA_H), aM0,aM1,aM2,aM3);
                ldsm4(aAddr + (SA_L - SA_H), aL0,aL1,aL2,aL3);
                #pragma unroll
                for (int h = 0; h < 2; h++) {
                    uint32_t bH0,bH1,bH2,bH3, bM0,bM1,bM2,bM3, bL0,bL1,bL2,bL3;
                    uint32_t bAddr = bBase + (uint32_t)(16*h)*PITCH + 32*ks;
                    ldsm4(bAddr,                 bH0,bH1,bH2,bH3);
                    ldsm4(bAddr + (SB_M - SB_H), bM0,bM1,bM2,bM3);
                    ldsm4(bAddr + (SB_L - SB_H), bL0,bL1,bL2,bL3);
                    float* cL = c[2*h];
                    float* cR = c[2*h+1];
                    hmma(cL, aH0,aH1,aH2,aH3, bH0,bH1);
                    hmma(cL, aH0,aH1,aH2,aH3, bM0,bM1);
                    hmma(cL, aM0,aM1,aM2,aM3, bH0,bH1);
                    hmma(cL, aM0,aM1,aM2,aM3, bM0,bM1);
                    hmma(cL, aH0,aH1,aH2,aH3, bL0,bL1);
                    hmma(cL, aL0,aL1,aL2,aL3, bH0,bH1);
                    hmma(cR, aH0,aH1,aH2,aH3, bH2,bH3);
                    hmma(cR, aH0,aH1,aH2,aH3, bM2,bM3);
                    hmma(cR, aM0,aM1,aM2,aM3, bH2,bH3);
                    hmma(cR, aM0,aM1,aM2,aM3, bM2,bM3);
                    hmma(cR, aH0,aH1,aH2,aH3, bL2,bL3);
                    hmma(cR, aL0,aL1,aL2,aL3, bH2,bH3);
                }
            }
        }

        // ---- state machine: runs IN-REGISTER in the 4 logit-row threads per half ----
        if (isSM) {
            if (t > 0) {
                int tp = t - 1;
                bool inRespP = (tp >= 20) && (tp < 35);
                #pragma unroll
                for (int s = 0; s < 8; s++) {
                    float lg = c[s>>1][s&1] + b0;
                    int col = n0 + 8*(s>>1) + 2*q + (s&1);
                    bool lic = (licM >> s) & 1;
                    bool trig = inRespP && !lic && (lg > 0.0f);   // sigmoid(x)>0.5 <=> x>0
                    if (trig) { lickT8[s] = tp; licM |= 1u << s; }
                    bool lic2 = (licM >> s) & 1;
                    bool u5 = lic2 && (tp >= lickT8[s]) && (tp < lickT8[s] + 5);
                    bool u4 = ((iAM >> s) & 1) || (u5 && ((isRewM8 >> s) & 1));
                    out[OFFZ + (size_t)(bb + col)*TSTEPS + tp] = 1.0f / (1.0f + __expf(-lg));
                    size_t ub = OFFU + (size_t)(bb + col)*(TSTEPS*7) + (size_t)tp*7;
                    out[ub + 4] = u4 ? 1.0f : 0.0f;
                    out[ub + 5] = u5 ? 1.0f : 0.0f;
                }
            }
            if (!last) {
                iAM = 0;
                #pragma unroll
                for (int s = 0; s < 8; s++) {
                    bool lic = (licM >> s) & 1;
                    bool irw = (isRewM8 >> s) & 1;
                    bool ib  = (insBM8 >> s) & 1;
                    bool ifd = (insFM >> s) & 1;
                    bool delivered = ifd || (lic && irw);
                    if (ib && !delivered && (t == 30)) { insFM |= 1u << s; ifd = true; }
                    bool iA = ifd && (t >= 30) && (t < 35);
                    if (iA) iAM |= 1u << s;
                    bool lickDyn = lic && (t > lickT8[s]) && (t < lickT8[s] + 5);
                    int col = n0 + 8*(s>>1) + 2*q + (s&1);
                    smCab[col] = make_float2((iA ? 1.0f : 0.0f) + ((lickDyn && irw) ? 1.0f : 0.0f),
                                             lickDyn ? 1.0f : 0.0f);
                }
            } else {
                #pragma unroll
                for (int s = 0; s < 8; s++) {
                    int col = n0 + 8*(s>>1) + 2*q + (s&1);
                    bool lic = (licM >> s) & 1;
                    bool irw = (isRewM8 >> s) & 1;
                    bool ifd = (insFM >> s) & 1;
                    out[OFFL + (size_t)(bb + col)] = lic ? 1.0f : 0.0f;
                    out[OFFR + (size_t)(bb + col)] = (ifd || (lic && irw)) ? 1.0f : 0.0f;
                }
            }
        }

        // ---- park staged noise (this half's region) ----
        if (!last) {
            #pragma unroll
            for (int i = 0; i < 4; i++) {
                int idx = hid + 256*i;
                if (idx < 800) {
                    int trl = idx / 25, qq = idx - 25*trl;
                    *reinterpret_cast<float4*>(nzH + trl*108 + 4*qq) = stg[i];
                }
            }
        }
        HBAR();   // half-barrier #1: cab + noise visible; MMA B-reads complete

        // ---- epilogue: y(t) from D + inputs; publish y splits ----
        if (!last && act) {
            const bool inStim = (t >= 10) && (t < 15);
            const float a6 = ((t >= 20) && (t < 35)) ? 1.0f : 0.0f;
            const bool doAdd = (t >= 20);
            #pragma unroll
            for (int nt = 0; nt < 4; nt++) {
                int col0 = n0 + 8*nt + 2*q;
                #pragma unroll
                for (int e = 0; e < 2; e++) {
                    int col = col0 + e;
                    int lcol = col - n0;
                    float2 cab = doAdd ? smCab[col] : make_float2(0.f, 0.f);
                    int sv = inStim ? smStim[col] : 0;
                    if (v0) {
                        float p = c[nt][e];
                        if (inStim) p += (sv==0)?wiA.x:(sv==1)?wiA.y:(sv==2)?wiA.z:wiA.w;
                        p = fmaf(a6, w6A, p);
                        if (doAdd) p = fmaf(cab.x, w4A, fmaf(cab.y, w5A, p));
                        p = fmaf(NSCALE, nzH[lcol*108 + u0], p);
                        float yv = 0.8f*yA[2*nt+e] + 0.2f*fmaxf(p, 0.0f);
                        yA[2*nt+e] = yv;
                        split_store(smc+SB_H, smc+SB_M, smc+SB_L, col*PITCH + 2*u0, yv);
                    }
                    if (v1) {
                        float p = c[nt][2+e];
                        if (inStim) p += (sv==0)?wiB.x:(sv==1)?wiB.y:(sv==2)?wiB.z:wiB.w;
                        p = fmaf(a6, w6B, p);
                        if (doAdd) p = fmaf(cab.x, w4B, fmaf(cab.y, w5B, p));
                        p = fmaf(NSCALE, nzH[lcol*108 + u1], p);
                        float yv = 0.8f*yB[2*nt+e] + 0.2f*fmaxf(p, 0.0f);
                        yB[2*nt+e] = yv;
                        split_store(smc+SB_H, smc+SB_M, smc+SB_L, col*PITCH + 2*u1, yv);
                    }
                }
            }
            if (t == TSTEPS - 1) {
                #pragma unroll
                for (int nt = 0; nt < 4; nt++) {
                    int col0 = n0 + 8*nt + 2*q;
                    #pragma unroll
                    for (int e = 0; e < 2; e++) {
                        if (v0) out[OFFYF + (size_t)(bb+col0+e)*NU + u0] = yA[2*nt+e];
                        if (v1) out[OFFYF + (size_t)(bb+col0+e)*NU + u1] = yB[2*nt+e];
                    }
                }
            }
        }
        HBAR();   // half-barrier #2: publishes visible before next round's MMA
    }

    // ---- static per-(trial,t) outputs ----
    if (tid < 64) {
        int s = tid;
        int b = bb + s;
        int sv = smStim[s];
        bool irw = (sv == rewI[b]);
        for (int t = 0; t < TSTEPS; t++) {
            bool resp = (t >= 20) && (t < 35);
            bool stm  = (t >= 10) && (t < 15);
            float* ub = out + OFFU + (size_t)b*(TSTEPS*7) + (size_t)t*7;
            ub[0] = (stm && sv == 0) ? 1.0f : 0.0f;
            ub[1] = (stm && sv == 1) ? 1.0f : 0.0f;
            ub[2] = (stm && sv == 2) ? 1.0f : 0.0f;
            ub[3] = (stm && sv == 3) ? 1.0f : 0.0f;
            ub[6] = resp ? 1.0f : 0.0f;
            out[OFFT  + (size_t)b*TSTEPS + t] = (irw && resp) ? 1.0f : 0.0f;
            out[OFFRS + (size_t)b*TSTEPS + t] = resp ? 1.0f : 0.0f;
        }
    }
}

extern "C" void kernel_launch(void* const* d_in, const int* in_sizes, int n_in,
                              void* d_out, int out_size) {
    const float* y0     = (const float*)d_in[0];
    const float* noise  = (const float*)d_in[1];
    const int*   stim   = (const int*)  d_in[2];
    const int*   rew    = (const int*)  d_in[3];
    const int*   instr  = (const int*)  d_in[4];
    const float* WinRaw = (const float*)d_in[5];
    const float* Wrec   = (const float*)d_in[6];
    const float* brec   = (const float*)d_in[7];
    const float* wout   = (const float*)d_in[8];
    const float* bout   = (const float*)d_in[9];
    float* out = (float*)d_out;

    cudaFuncSetAttribute(rnn_hmma_kernel,
                         cudaFuncAttributeMaxDynamicSharedMemorySize, SMEM_TOTAL);
    rnn_hmma_kernel<<<BTOT/64, 512, SMEM_TOTAL>>>(
        y0, noise, stim, rew, instr, WinRaw, Wrec, brec, wout, bout, out);
}

// round 17
// speedup vs baseline: 1.6445x; 1.6445x over previous
#include <cuda_runtime.h>
#include <cuda_fp16.h>
#include <cstdint>
#include <cstddef>

#define NU      100
#define TSTEPS  60
#define BTOT    8192
static const size_t OFFU  = 0;
static const size_t OFFT  = 3440640;
static const size_t OFFRS = 3932160;
static const size_t OFFL  = 4423680;
static const size_t OFFR  = 4431872;
static const size_t OFFZ  = 4440064;
static const size_t OFFYF = 4931584;

#define NSCALE 0.09486832980505138f

// GEMM per block per step: D[112,64] = A[112 x 112] * B^T, fp16 2-split (h+m), 3 passes
// (hh, hm, mh); dropped mm ~ 2^-22. fp32 accum.
// A[m][k] pitch 272B: rows 0-99 = Wrec, row 100 = w_out, k-col 111 = b_rec.
// B stored [k][n] pitch 144B (row-major k), loaded with ldmatrix.trans -> same
// fragments as non-trans on [n][k]. B row 111 = 1.0 (bias lane).
// 512 threads = 16 warps; warp = (mw, nw): mw<7 owns M rows 16mw..16mw+15,
// nw owns N cols 32nw..32nw+31.
#define PITCHA 272
#define PITCHB 144
#define SA_H 0
#define SA_M 30464
#define SB_H 60928
#define SB_M 77056
#define S_NZ   93184    // 64 x 108 floats
#define S_STIM 120832
#define S_CAB  121088
#define S_LOG  121600
#define SMEM_TOTAL 121856

__device__ __forceinline__ uint32_t smem_u32(const void* p){
    uint32_t a;
    asm("{ .reg .u64 t; cvta.to.shared.u64 t, %1; cvt.u32.u64 %0, t; }" : "=r"(a) : "l"(p));
    return a;
}
__device__ __forceinline__ void ldsm4(uint32_t addr, uint32_t &r0, uint32_t &r1, uint32_t &r2, uint32_t &r3){
    asm volatile("ldmatrix.sync.aligned.m8n8.x4.shared.b16 {%0,%1,%2,%3}, [%4];"
        : "=r"(r0), "=r"(r1), "=r"(r2), "=r"(r3) : "r"(addr));
}
__device__ __forceinline__ void ldsm4t(uint32_t addr, uint32_t &r0, uint32_t &r1, uint32_t &r2, uint32_t &r3){
    asm volatile("ldmatrix.sync.aligned.m8n8.x4.trans.shared.b16 {%0,%1,%2,%3}, [%4];"
        : "=r"(r0), "=r"(r1), "=r"(r2), "=r"(r3) : "r"(addr));
}
__device__ __forceinline__ void hmma(float* c, uint32_t a0, uint32_t a1, uint32_t a2, uint32_t a3,
                                     uint32_t b0, uint32_t b1){
    asm volatile("mma.sync.aligned.m16n8k16.row.col.f32.f16.f16.f32 "
        "{%0,%1,%2,%3},{%4,%5,%6,%7},{%8,%9},{%0,%1,%2,%3};"
        : "+f"(c[0]), "+f"(c[1]), "+f"(c[2]), "+f"(c[3])
        : "r"(a0), "r"(a1), "r"(a2), "r"(a3), "r"(b0), "r"(b1));
}
// fp16 2-split scalar store (init paths)
__device__ __forceinline__ void split2_store(char* bh, char* bm, int off, float v){
    __half h = __float2half_rn(v);
    __half m = __float2half_rn(v - __half2float(h));
    *(__half*)(bh + off) = h;
    *(__half*)(bm + off) = m;
}

__global__ __launch_bounds__(512)
void rnn_hmma_kernel(
    const float* __restrict__ y0,      const float* __restrict__ noise,
    const int*   __restrict__ stimI,   const int*   __restrict__ rewI,
    const int*   __restrict__ instrI,
    const float* __restrict__ WinRaw,  const float* __restrict__ Wrec,
    const float* __restrict__ brec,    const float* __restrict__ wout,
    const float* __restrict__ bout,
    float* __restrict__ out)
{
    extern __shared__ char smc[];
    const uint32_t smb = smem_u32(smc);
    float*  smNz   = reinterpret_cast<float*>(smc + S_NZ);
    int*    smStim = reinterpret_cast<int*>(smc + S_STIM);
    float2* smCab  = reinterpret_cast<float2*>(smc + S_CAB);
    float*  smLog  = reinterpret_cast<float*>(smc + S_LOG);

    const int tid  = threadIdx.x;
    const int lane = tid & 31;
    const int warp = tid >> 5;
    const int bb   = blockIdx.x * 64;

    // ---- zero A/B split buffers ----
    for (int i = tid; i < S_NZ/16; i += 512)
        reinterpret_cast<uint4*>(smc)[i] = make_uint4(0,0,0,0);
    __syncthreads();

    // ---- fill A splits ([m][k]) ----
    for (int idx = tid; idx < NU*NU; idx += 512) {
        int m = idx / NU, k = idx - m*NU;
        split2_store(smc+SA_H, smc+SA_M, m*PITCHA + 2*k, Wrec[idx]);
    }
    for (int k = tid; k < NU; k += 512)
        split2_store(smc+SA_H, smc+SA_M, 100*PITCHA + 2*k, wout[k]);
    for (int m = tid; m < NU; m += 512)
        split2_store(smc+SA_H, smc+SA_M, m*PITCHA + 2*111, brec[m]);
    // B row 111 = 1.0 (hi only), [k][n] layout
    for (int n = tid; n < 64; n += 512)
        *(__half*)(smc + SB_H + 111*PITCHB + 2*n) = __float2half_rn(1.0f);
    // B = y0 splits, [k][n]
    for (int idx = tid; idx < 64*NU; idx += 512) {
        int n = idx / NU, k = idx - n*NU;
        split2_store(smc+SB_H, smc+SB_M, k*PITCHB + 2*n, y0[(size_t)(bb + n)*NU + k]);
    }

    // ---- per-trial state (thread s<64 owns trial bb+s) ----
    bool licked=false, instrF=false, isRew=false, instrB=false, iAprev=false;
    int lickT = TSTEPS + 1;
    if (tid < 64) {
        int b = bb + tid;
        int sv = stimI[b];
        smStim[tid] = sv;
        isRew  = (sv == rewI[b]);
        instrB = (instrI[b] > 0);
    }
    const float b0 = bout[0];

    // ---- per-thread MMA geometry ----
    const int g = lane >> 2, q = lane & 3;
    const int mw = warp >> 1, nw = warp & 1;
    const int m0 = 16*mw, n0 = 32*nw;
    const int u0 = m0 + g, u1 = u0 + 8;
    const bool act = (mw < 7);
    const bool v0 = act && (u0 < NU);
    const bool v1 = act && (u1 < NU);

    float4 wiA = make_float4(0,0,0,0), wiB = make_float4(0,0,0,0);
    float w4A=0,w5A=0,w6A=0,w4B=0,w5B=0,w6B=0;
    if (v0) {
        wiA = make_float4(fabsf(WinRaw[u0*7+0]), fabsf(WinRaw[u0*7+1]),
                          fabsf(WinRaw[u0*7+2]), fabsf(WinRaw[u0*7+3]));
        w4A = fabsf(WinRaw[u0*7+4]); w5A = fabsf(WinRaw[u0*7+5]); w6A = fabsf(WinRaw[u0*7+6]);
    }
    if (v1) {
        wiB = make_float4(fabsf(WinRaw[u1*7+0]), fabsf(WinRaw[u1*7+1]),
                          fabsf(WinRaw[u1*7+2]), fabsf(WinRaw[u1*7+3]));
        w4B = fabsf(WinRaw[u1*7+4]); w5B = fabsf(WinRaw[u1*7+5]); w6B = fabsf(WinRaw[u1*7+6]);
    }

    // y state: 2 units x 8 cols; col(nt,e) = n0 + 8*nt + 2*q + e, nt<4
    float yA[8], yB[8];
    #pragma unroll
    for (int nt = 0; nt < 4; nt++) {
        int col = n0 + 8*nt + 2*q;
        yA[2*nt]   = v0 ? y0[(size_t)(bb+col  )*NU + u0] : 0.0f;
        yA[2*nt+1] = v0 ? y0[(size_t)(bb+col+1)*NU + u0] : 0.0f;
        yB[2*nt]   = v1 ? y0[(size_t)(bb+col  )*NU + u1] : 0.0f;
        yB[2*nt+1] = v1 ? y0[(size_t)(bb+col+1)*NU + u1] : 0.0f;
    }

    // ldmatrix addresses: A non-trans on [m][k]; B trans on [k][n]
    const uint32_t rbA = (uint32_t)(((lane & 7) + ((lane >> 3) & 1)*8)*PITCHA + ((lane >> 4) & 1)*16);
    const uint32_t rbB = (uint32_t)(((lane & 7) + ((lane >> 3) & 1)*8)*PITCHB + ((lane >> 4) & 1)*16);
    const uint32_t aBase = smb + SA_H + (uint32_t)m0*PITCHA + rbA;
    const uint32_t bBase = smb + SB_H + (uint32_t)n0*2 + rbB;

    __syncthreads();

    // ==================== time loop (61 rounds) ====================
    for (int t = 0; t <= TSTEPS; t++) {
        const bool last = (t == TSTEPS);

        // ---- stage noise (regs now, smem later; overlaps MMA) ----
        float4 stg[4];
        if (!last) {
            #pragma unroll
            for (int i = 0; i < 4; i++) {
                int idx = tid + 512*i;
                if (idx < 1600) {
                    int tr = idx / 25, qq = idx - 25*tr;
                    stg[i] = *reinterpret_cast<const float4*>(
                        noise + (size_t)(bb + tr)*(TSTEPS*NU) + (size_t)t*NU + 4*qq);
                }
            }
        }

        // ---- MMA: 3 fp16-split passes (hh, hm, mh), k-grouped; 16x32 tile/warp ----
        float c[4][4];
        #pragma unroll
        for (int nt = 0; nt < 4; nt++) { c[nt][0]=0.f; c[nt][1]=0.f; c[nt][2]=0.f; c[nt][3]=0.f; }
        if (act) {
            #pragma unroll
            for (int ks = 0; ks < 7; ks++) {
                uint32_t aH0,aH1,aH2,aH3, aM0,aM1,aM2,aM3;
                uint32_t aAddr = aBase + 32*ks;
                ldsm4(aAddr,                 aH0,aH1,aH2,aH3);
                ldsm4(aAddr + (SA_M - SA_H), aM0,aM1,aM2,aM3);
                #pragma unroll
                for (int h = 0; h < 2; h++) {
                    uint32_t bH0,bH1,bH2,bH3, bM0,bM1,bM2,bM3;
                    uint32_t bAddr = bBase + (uint32_t)(16*PITCHB)*ks + 32*h;
                    ldsm4t(bAddr,                 bH0,bH1,bH2,bH3);
                    ldsm4t(bAddr + (SB_M - SB_H), bM0,bM1,bM2,bM3);
                    float* cL = c[2*h];
                    float* cR = c[2*h+1];
                    hmma(cL, aH0,aH1,aH2,aH3, bH0,bH1);  // hh
                    hmma(cL, aH0,aH1,aH2,aH3, bM0,bM1);  // hm
                    hmma(cL, aM0,aM1,aM2,aM3, bH0,bH1);  // mh
                    hmma(cR, aH0,aH1,aH2,aH3, bH2,bH3);
                    hmma(cR, aH0,aH1,aH2,aH3, bM2,bM3);
                    hmma(cR, aM0,aM1,aM2,aM3, bH2,bH3);
                }
            }
        }

        // ---- logit row (unit 100 = mw 6, g==4) -> smem ----
        if (mw == 6 && g == 4) {
            #pragma unroll
            for (int nt = 0; nt < 4; nt++) {
                smLog[n0 + 8*nt + 2*q]     = c[nt][0];
                smLog[n0 + 8*nt + 2*q + 1] = c[nt][1];
            }
        }
        // ---- park staged noise in smem ----
        if (!last) {
            #pragma unroll
            for (int i = 0; i < 4; i++) {
                int idx = tid + 512*i;
                if (idx < 1600) {
                    int tr = idx / 25, qq = idx - 25*tr;
                    *reinterpret_cast<float4*>(smNz + tr*108 + 4*qq) = stg[i];
                }
            }
        }
        __syncthreads();

        // ---- state machine (threads < 64) ----
        if (tid < 64) {
            int s = tid;
            if (t > 0) {
                int tp = t - 1;
                float lg = smLog[s] + b0;
                bool inRespP = (tp >= 20) && (tp < 35);
                bool trig = inRespP && !licked && (lg > 0.0f);   // sigmoid(x)>0.5 <=> x>0
                if (trig) { lickT = tp; licked = true; }
                bool u5 = licked && (tp >= lickT) && (tp < lickT + 5);
                bool u4 = iAprev || (u5 && isRew);
                out[OFFZ + (size_t)(bb + s)*TSTEPS + tp] = 1.0f / (1.0f + __expf(-lg));
                size_t ub = OFFU + (size_t)(bb + s)*(TSTEPS*7) + (size_t)tp*7;
                out[ub + 4] = u4 ? 1.0f : 0.0f;
                out[ub + 5] = u5 ? 1.0f : 0.0f;
            }
            if (!last) {
                bool delivered = instrF || (licked && isRew);
                if (instrB && !delivered && (t == 30)) instrF = true;
                bool iA = instrF && (t >= 30) && (t < 35);
                iAprev = iA;
                bool lickDyn = licked && (t > lickT) && (t < lickT + 5);
                smCab[s] = make_float2((iA ? 1.0f : 0.0f) + ((lickDyn && isRew) ? 1.0f : 0.0f),
                                       lickDyn ? 1.0f : 0.0f);
            } else {
                out[OFFL + (size_t)(bb + s)] = licked ? 1.0f : 0.0f;
                out[OFFR + (size_t)(bb + s)] = (instrF || (licked && isRew)) ? 1.0f : 0.0f;
            }
        }
        __syncthreads();

        // ---- epilogue: y(t) from D + inputs; publish packed fp16 splits ----
        if (!last && act) {
            const bool inStim = (t >= 10) && (t < 15);
            const float a6 = ((t >= 20) && (t < 35)) ? 1.0f : 0.0f;
            const bool doAdd = (t >= 20);
            #pragma unroll
            for (int nt = 0; nt < 4; nt++) {
                int col0 = n0 + 8*nt + 2*q;
                float yv0A=0.f, yv1A=0.f, yv0B=0.f, yv1B=0.f;
                #pragma unroll
                for (int e = 0; e < 2; e++) {
                    int col = col0 + e;
                    float2 cab = doAdd ? smCab[col] : make_float2(0.f, 0.f);
                    int sv = inStim ? smStim[col] : 0;
                    if (v0) {
                        float p = c[nt][e];
                        if (inStim) p += (sv==0)?wiA.x:(sv==1)?wiA.y:(sv==2)?wiA.z:wiA.w;
                        p = fmaf(a6, w6A, p);
                        if (doAdd) p = fmaf(cab.x, w4A, fmaf(cab.y, w5A, p));
                        p = fmaf(NSCALE, smNz[col*108 + u0], p);
                        float yv = 0.8f*yA[2*nt+e] + 0.2f*fmaxf(p, 0.0f);
                        yA[2*nt+e] = yv;
                        if (e) yv1A = yv; else yv0A = yv;
                    }
                    if (v1) {
                        float p = c[nt][2+e];
                        if (inStim) p += (sv==0)?wiB.x:(sv==1)?wiB.y:(sv==2)?wiB.z:wiB.w;
                        p = fmaf(a6, w6B, p);
                        if (doAdd) p = fmaf(cab.x, w4B, fmaf(cab.y, w5B, p));
                        p = fmaf(NSCALE, smNz[col*108 + u1], p);
                        float yv = 0.8f*yB[2*nt+e] + 0.2f*fmaxf(p, 0.0f);
                        yB[2*nt+e] = yv;
                        if (e) yv1B = yv; else yv0B = yv;
                    }
                }
                // packed conflict-free STS.32: addr = u*144 + col0*2
                if (v0) {
                    __half h0 = __float2half_rn(yv0A), h1 = __float2half_rn(yv1A);
                    __half m0 = __float2half_rn(yv0A - __half2float(h0));
                    __half m1 = __float2half_rn(yv1A - __half2float(h1));
                    *reinterpret_cast<__half2*>(smc + SB_H + u0*PITCHB + 2*col0) = __halves2half2(h0, h1);
                    *reinterpret_cast<__half2*>(smc + SB_M + u0*PITCHB + 2*col0) = __halves2half2(m0, m1);
                }
                if (v1) {
                    __half h0 = __float2half_rn(yv0B), h1 = __float2half_rn(yv1B);
                    __half m0 = __float2half_rn(yv0B - __half2float(h0));
                    __half m1 = __float2half_rn(yv1B - __half2float(h1));
                    *reinterpret_cast<__half2*>(smc + SB_H + u1*PITCHB + 2*col0) = __halves2half2(h0, h1);
                    *reinterpret_cast<__half2*>(smc + SB_M + u1*PITCHB + 2*col0) = __halves2half2(m0, m1);
                }
            }
            if (t == TSTEPS - 1) {
                #pragma unroll
                for (int nt = 0; nt < 4; nt++) {
                    int col0 = n0 + 8*nt + 2*q;
                    #pragma unroll
                    for (int e = 0; e < 2; e++) {
                        if (v0) out[OFFYF + (size_t)(bb+col0+e)*NU + u0] = yA[2*nt+e];
                        if (v1) out[OFFYF + (size_t)(bb+col0+e)*NU + u1] = yB[2*nt+e];
                    }
                }
            }
        }
        __syncthreads();
    }

    // ---- static per-(trial,t) outputs ----
    if (tid < 64) {
        int s = tid;
        int sv = smStim[s];
        size_t b = (size_t)(bb + s);
        for (int t = 0; t < TSTEPS; t++) {
            bool resp = (t >= 20) && (t < 35);
            bool stm  = (t >= 10) && (t < 15);
            float* ub = out + OFFU + b*(TSTEPS*7) + (size_t)t*7;
            ub[0] = (stm && sv == 0) ? 1.0f : 0.0f;
            ub[1] = (stm && sv == 1) ? 1.0f : 0.0f;
            ub[2] = (stm && sv == 2) ? 1.0f : 0.0f;
            ub[3] = (stm && sv == 3) ? 1.0f : 0.0f;
            ub[6] = resp ? 1.0f : 0.0f;
            out[OFFT  + b*TSTEPS + t] = (isRew && resp) ? 1.0f : 0.0f;
            out[OFFRS + b*TSTEPS + t] = resp ? 1.0f : 0.0f;
        }
    }
}

extern "C" void kernel_launch(void* const* d_in, const int* in_sizes, int n_in,
                              void* d_out, int out_size) {
    const float* y0     = (const float*)d_in[0];
    const float* noise  = (const float*)d_in[1];
    const int*   stim   = (const int*)  d_in[2];
    const int*   rew    = (const int*)  d_in[3];
    const int*   instr  = (const int*)  d_in[4];
    const float* WinRaw = (const float*)d_in[5];
    const float* Wrec   = (const float*)d_in[6];
    const float* brec   = (const float*)d_in[7];
    const float* wout   = (const float*)d_in[8];
    const float* bout   = (const float*)d_in[9];
    float* out = (float*)d_out;

    cudaFuncSetAttribute(rnn_hmma_kernel,
                         cudaFuncAttributeMaxDynamicSharedMemorySize, SMEM_TOTAL);
    rnn_hmma_kernel<<<BTOT/64, 512, SMEM_TOTAL>>>(
        y0, noise, stim, rew, instr, WinRaw, Wrec, brec, wout, bout, out);
}